// round 3
// baseline (speedup 1.0000x reference)
#include <cuda_runtime.h>
#include <math.h>

#define BB    8
#define NN    2048
#define DIN   512
#define DOUT  256
#define NBUCK 20
#define ROWS  (BB*NN)   // 16384

// ---------------- scratch (static __device__, no allocations) ----------------
__device__ float g_q[ROWS*DOUT];   // 16 MB
__device__ float g_k[ROWS*DOUT];   // 16 MB
__device__ float g_s[ROWS];        // v . Ws per (b,m)
__device__ float g_gate[NBUCK];
__device__ float g_wvs[DIN];       // Wv^T @ Ws
__device__ float g_bvs;

// ---------------- prep: gate LUT + collapsed V path ----------------
__global__ void prep_kernel(const float* __restrict__ Wv, const float* __restrict__ bv,
                            const float* __restrict__ Ws, const float* __restrict__ remb,
                            const float* __restrict__ rw) {
    int t = threadIdx.x;
    if (t < NBUCK) {
        float z = rw[0] * remb[t];
        g_gate[t] = 1.f / (1.f + expf(-z));
    }
    if (t < DIN) {
        float acc = 0.f;
        for (int o = 0; o < DOUT; o++) acc += Wv[o*DIN + t] * Ws[o];
        g_wvs[t] = acc;
    }
    if (t == 0) {
        float acc = 0.f;
        for (int o = 0; o < DOUT; o++) acc += bv[o] * Ws[o];
        g_bvs = acc;
    }
}

// ---------------- s[b,m] = x . wvs + bvs  (1 warp / row) ----------------
__global__ void s_kernel(const float* __restrict__ x) {
    int row  = blockIdx.x * 8 + (threadIdx.x >> 5);
    int lane = threadIdx.x & 31;
    const float* xr = x + (size_t)row * DIN;
    float acc = 0.f;
    #pragma unroll
    for (int d = lane; d < DIN; d += 32) acc += xr[d] * g_wvs[d];
    #pragma unroll
    for (int s = 16; s; s >>= 1) acc += __shfl_xor_sync(0xffffffffu, acc, s);
    if (lane == 0) g_s[row] = acc + g_bvs;
}

// ---------------- Q/K projection: 128x128 tile SGEMM, BK=16, 8x8 micro ----------------
__global__ __launch_bounds__(256) void qk_gemm(const float* __restrict__ x,
                                               const float* __restrict__ Wq, const float* __restrict__ bq,
                                               const float* __restrict__ Wk, const float* __restrict__ bk) {
    const int row0 = blockIdx.x * 128;
    int ycol = blockIdx.y;                 // 0..3  (0,1 -> Q cols; 2,3 -> K cols)
    const float* W; const float* bias; float* outp;
    if (ycol < 2) { W = Wq; bias = bq; outp = g_q; }
    else          { W = Wk; bias = bk; outp = g_k; ycol -= 2; }
    const int col0 = ycol * 128;

    __shared__ float As[16][132];   // k-major [k][row]
    __shared__ float Bs[16][132];   // k-major [k][col]

    const int t  = threadIdx.x;
    const int tx = t & 15, ty = t >> 4;

    float acc[8][8];
    #pragma unroll
    for (int i = 0; i < 8; i++)
        #pragma unroll
        for (int j = 0; j < 8; j++) acc[i][j] = 0.f;

    for (int k0 = 0; k0 < DIN; k0 += 16) {
        #pragma unroll
        for (int it = 0; it < 2; it++) {
            int idx = t + it * 256;          // 0..511 float4 slots
            int r   = idx >> 2;
            int kq  = (idx & 3) * 4;
            float4 va = *(const float4*)(x + (size_t)(row0 + r) * DIN + k0 + kq);
            As[kq+0][r] = va.x; As[kq+1][r] = va.y; As[kq+2][r] = va.z; As[kq+3][r] = va.w;
            float4 vb = *(const float4*)(W + (size_t)(col0 + r) * DIN + k0 + kq);
            Bs[kq+0][r] = vb.x; Bs[kq+1][r] = vb.y; Bs[kq+2][r] = vb.z; Bs[kq+3][r] = vb.w;
        }
        __syncthreads();
        #pragma unroll
        for (int kk = 0; kk < 16; kk++) {
            float4 a0 = *(const float4*)&As[kk][ty*8];
            float4 a1 = *(const float4*)&As[kk][ty*8+4];
            float4 b0 = *(const float4*)&Bs[kk][tx*8];
            float4 b1 = *(const float4*)&Bs[kk][tx*8+4];
            float av[8] = {a0.x,a0.y,a0.z,a0.w,a1.x,a1.y,a1.z,a1.w};
            float bw[8] = {b0.x,b0.y,b0.z,b0.w,b1.x,b1.y,b1.z,b1.w};
            #pragma unroll
            for (int i = 0; i < 8; i++)
                #pragma unroll
                for (int j = 0; j < 8; j++) acc[i][j] += av[i] * bw[j];
        }
        __syncthreads();
    }

    float bv8[8];
    #pragma unroll
    for (int j = 0; j < 8; j++) bv8[j] = bias[col0 + tx*8 + j];
    #pragma unroll
    for (int i = 0; i < 8; i++) {
        size_t base = (size_t)(row0 + ty*8 + i) * DOUT + col0 + tx*8;
        float4 o0 = make_float4(acc[i][0]+bv8[0], acc[i][1]+bv8[1], acc[i][2]+bv8[2], acc[i][3]+bv8[3]);
        float4 o1 = make_float4(acc[i][4]+bv8[4], acc[i][5]+bv8[5], acc[i][6]+bv8[6], acc[i][7]+bv8[7]);
        *(float4*)(outp + base)     = o0;
        *(float4*)(outp + base + 4) = o1;
    }
}

// ---------------- fused gated attention + head ----------------
// Shared layout (floats): Qs[256][132] | Ks[256][68] | s_sh[64] | gtab[20] | rankN[128](int) | rankM[64](int)
#define Q_STR 132
#define K_STR 68
#define Q_OFF 0
#define K_OFF (256*Q_STR)            // 33792
#define S_OFF (K_OFF + 256*K_STR)    // 51200
#define G_OFF (S_OFF + 64)           // 51264
#define RI_OFF (G_OFF + 20)          // 51284 (int region)
#define ATTN_SMEM_BYTES ((RI_OFF + 192) * 4)   // 205904

__global__ __launch_bounds__(256) void attn_kernel(const long long* __restrict__ pr,
                                                   const float* __restrict__ bs_p,
                                                   float* __restrict__ out) {
    extern __shared__ float sh[];
    float* Qs   = sh + Q_OFF;
    float* Ks   = sh + K_OFF;
    float* s_sh = sh + S_OFF;
    float* gt   = sh + G_OFF;
    int*   rankN = (int*)(sh + RI_OFF);
    int*   rankM = rankN + 128;

    const int b  = blockIdx.y;
    const int n0 = blockIdx.x * 128;
    const int t  = threadIdx.x;
    const int tx = t & 15, ty = t >> 4;

    if (t < NBUCK) gt[t] = g_gate[t];
    if (t < 128)   rankN[t] = (int)pr[(size_t)b*NN + n0 + t];

    // load Q tile [128 rows][256] -> k-major shared
    const float* qb = g_q + ((size_t)b*NN + n0) * DOUT;
    #pragma unroll
    for (int it = 0; it < 32; it++) {
        int idx = t + it * 256;      // 0..8191 float4 slots
        int r   = idx >> 6;
        int o4  = idx & 63;
        float4 v = *(const float4*)(qb + (size_t)r * DOUT + o4*4);
        int o = o4 * 4;
        Qs[(o+0)*Q_STR + r] = v.x; Qs[(o+1)*Q_STR + r] = v.y;
        Qs[(o+2)*Q_STR + r] = v.z; Qs[(o+3)*Q_STR + r] = v.w;
    }
    __syncthreads();

    int rn[8];
    #pragma unroll
    for (int i = 0; i < 8; i++) rn[i] = rankN[ty*8 + i];

    float m_i[8], l_i[8], a_i[8];
    #pragma unroll
    for (int i = 0; i < 8; i++) { m_i[i] = -1e30f; l_i[i] = 0.f; a_i[i] = 0.f; }

    const float inv_scale = 0.0625f;  // 1/sqrt(DOUT)

    for (int m0 = 0; m0 < NN; m0 += 64) {
        const float* kb = g_k + ((size_t)b*NN + m0) * DOUT;
        #pragma unroll
        for (int it = 0; it < 16; it++) {
            int idx = t + it * 256;  // 0..4095 float4 slots
            int c   = idx >> 6;
            int o4  = idx & 63;
            float4 v = *(const float4*)(kb + (size_t)c * DOUT + o4*4);
            int o = o4 * 4;
            Ks[(o+0)*K_STR + c] = v.x; Ks[(o+1)*K_STR + c] = v.y;
            Ks[(o+2)*K_STR + c] = v.z; Ks[(o+3)*K_STR + c] = v.w;
        }
        if (t < 64) {
            s_sh[t]  = g_s[(size_t)b*NN + m0 + t];
            rankM[t] = (int)pr[(size_t)b*NN + m0 + t];
        }
        __syncthreads();

        float acc[8][4];
        #pragma unroll
        for (int i = 0; i < 8; i++)
            #pragma unroll
            for (int j = 0; j < 4; j++) acc[i][j] = 0.f;

        #pragma unroll 8
        for (int kk = 0; kk < DOUT; kk++) {
            float4 qa = *(const float4*)&Qs[kk*Q_STR + ty*8];
            float4 qc = *(const float4*)&Qs[kk*Q_STR + ty*8 + 4];
            float4 kv = *(const float4*)&Ks[kk*K_STR + tx*4];
            float av[8] = {qa.x,qa.y,qa.z,qa.w,qc.x,qc.y,qc.z,qc.w};
            float bw[4] = {kv.x,kv.y,kv.z,kv.w};
            #pragma unroll
            for (int i = 0; i < 8; i++)
                #pragma unroll
                for (int j = 0; j < 4; j++) acc[i][j] += av[i] * bw[j];
        }

        // gate + online softmax + weighted-s accumulation
        #pragma unroll
        for (int i = 0; i < 8; i++) {
            float sc[4];
            float rowmax = -1e30f;
            #pragma unroll
            for (int j = 0; j < 4; j++) {
                int dist = rn[i] - rankM[tx*4 + j];
                dist = dist < 0 ? -dist : dist;
                int bkt = dist / 5; if (bkt > NBUCK-1) bkt = NBUCK-1;
                float v = acc[i][j] * inv_scale * gt[bkt];
                sc[j] = v;
                rowmax = fmaxf(rowmax, v);
            }
            #pragma unroll
            for (int sft = 8; sft; sft >>= 1)
                rowmax = fmaxf(rowmax, __shfl_xor_sync(0xffffffffu, rowmax, sft));
            float newm = fmaxf(m_i[i], rowmax);
            float corr = __expf(m_i[i] - newm);
            float psum = 0.f, pa = 0.f;
            #pragma unroll
            for (int j = 0; j < 4; j++) {
                float e = __expf(sc[j] - newm);
                psum += e;
                pa   += e * s_sh[tx*4 + j];
            }
            #pragma unroll
            for (int sft = 8; sft; sft >>= 1) {
                psum += __shfl_xor_sync(0xffffffffu, psum, sft);
                pa   += __shfl_xor_sync(0xffffffffu, pa,   sft);
            }
            l_i[i] = l_i[i] * corr + psum;
            a_i[i] = a_i[i] * corr + pa;
            m_i[i] = newm;
        }
        __syncthreads();
    }

    if (tx == 0) {
        float bsv = bs_p[0];
        #pragma unroll
        for (int i = 0; i < 8; i++) {
            float z = a_i[i] / l_i[i] + bsv;
            out[(size_t)b*NN + n0 + ty*8 + i] = 1.f / (1.f + expf(-z));
        }
    }
}

// ---------------- launcher ----------------
extern "C" void kernel_launch(void* const* d_in, const int* in_sizes, int n_in,
                              void* d_out, int out_size) {
    const float*     x    = (const float*)d_in[0];
    const long long* pr   = (const long long*)d_in[1];
    const float*     Wq   = (const float*)d_in[2];
    const float*     bq   = (const float*)d_in[3];
    const float*     Wk   = (const float*)d_in[4];
    const float*     bk   = (const float*)d_in[5];
    const float*     Wv   = (const float*)d_in[6];
    const float*     bv   = (const float*)d_in[7];
    const float*     Ws   = (const float*)d_in[8];
    const float*     bs   = (const float*)d_in[9];
    const float*     remb = (const float*)d_in[10];
    const float*     rw   = (const float*)d_in[11];
    float* out = (float*)d_out;

    prep_kernel<<<1, 512>>>(Wv, bv, Ws, remb, rw);
    s_kernel<<<ROWS/8, 256>>>(x);
    dim3 g1(ROWS/128, 4);
    qk_gemm<<<g1, 256>>>(x, Wq, bq, Wk, bk);

    cudaFuncSetAttribute(attn_kernel, cudaFuncAttributeMaxDynamicSharedMemorySize, ATTN_SMEM_BYTES);
    dim3 g2(NN/128, BB);
    attn_kernel<<<g2, 256, ATTN_SMEM_BYTES>>>(pr, bs, out);
}

// round 7
// speedup vs baseline: 5.2841x; 5.2841x over previous
#include <cuda_runtime.h>
#include <cuda_bf16.h>
#include <stdint.h>
#include <math.h>

#define BB 8
#define NN 2048
#define DIN 512
#define DOUT 256
#define NBUCK 20
#define ROWS (BB*NN)   // 16384

// ---------------- scratch (static __device__, no allocations) ----------------
__device__ __nv_bfloat16 g_qb[ROWS*DOUT];   // 8 MB
__device__ __nv_bfloat16 g_kb[ROWS*DOUT];   // 8 MB
__device__ float g_s[ROWS];
__device__ float g_gate3[NBUCK];            // sigmoid(rw*emb) * log2(e) / 16
__device__ float g_wvs[DIN];
__device__ float g_bvs;

// ======================= helpers =======================
__device__ __forceinline__ uint32_t s2u(const void* p) {
    return (uint32_t)__cvta_generic_to_shared(p);
}

// swizzled smem byte offset for a 128row x 256col bf16 tile (512B rows, 32 16B chunks)
__device__ __forceinline__ uint32_t sw(uint32_t row, uint32_t chunk) {
    return row * 512u + ((chunk ^ (row & 7u)) << 4);
}

#define LDSM4(r0,r1,r2,r3,a)                                                     \
    asm volatile("ldmatrix.sync.aligned.m8n8.x4.shared.b16 {%0,%1,%2,%3}, [%4];" \
        : "=r"(r0), "=r"(r1), "=r"(r2), "=r"(r3) : "r"(a))

__device__ __forceinline__ void mma16816(float* c, uint32_t a0, uint32_t a1,
                                         uint32_t a2, uint32_t a3,
                                         uint32_t b0, uint32_t b1) {
    asm volatile("mma.sync.aligned.m16n8k16.row.col.f32.bf16.bf16.f32 "
        "{%0,%1,%2,%3}, {%4,%5,%6,%7}, {%8,%9}, {%0,%1,%2,%3};"
        : "+f"(c[0]), "+f"(c[1]), "+f"(c[2]), "+f"(c[3])
        : "r"(a0), "r"(a1), "r"(a2), "r"(a3), "r"(b0), "r"(b1));
}

#define CP16(dst, src) asm volatile("cp.async.cg.shared.global [%0], [%1], 16;" :: "r"(dst), "l"(src) : "memory")
#define CP_COMMIT()    asm volatile("cp.async.commit_group;" ::: "memory")
#define CP_WAIT0()     asm volatile("cp.async.wait_group 0;" ::: "memory")

// fast 2^y, rel err ~2e-6, pure fma pipe (no MUFU)
__device__ __forceinline__ float exp2_fast(float y) {
    float z = y + 12582912.0f;
    float f = y - (z - 12582912.0f);
    uint32_t n = (uint32_t)__float_as_int(z);
    float p = 1.3333558146e-3f;
    p = fmaf(p, f, 9.6181291e-3f);
    p = fmaf(p, f, 5.5504109e-2f);
    p = fmaf(p, f, 2.4022652e-1f);
    p = fmaf(p, f, 6.9314718e-1f);
    p = fmaf(p, f, 1.0f);
    return __uint_as_float((n << 23) + 0x3f800000u) * p;
}

// ======================= prep: gate LUT + collapsed V path =======================
__global__ void prep_kernel(const float* __restrict__ Wv, const float* __restrict__ bv,
                            const float* __restrict__ Ws, const float* __restrict__ remb,
                            const float* __restrict__ rw) {
    int t = threadIdx.x;
    if (t < NBUCK) {
        float zv = rw[0] * remb[t];
        float sg = 1.f / (1.f + expf(-zv));
        g_gate3[t] = sg * (1.44269504088896f / 16.0f);  // fold log2e / sqrt(DOUT)
    }
    if (t < DIN) {
        float acc = 0.f;
        for (int o = 0; o < DOUT; o++) acc += Wv[o*DIN + t] * Ws[o];
        g_wvs[t] = acc;
    }
    if (t == 0) {
        float acc = 0.f;
        for (int o = 0; o < DOUT; o++) acc += bv[o] * Ws[o];
        g_bvs = acc;
    }
}

// ======================= s[b,m] = x . wvs + bvs =======================
__global__ void s_kernel(const float* __restrict__ x) {
    int row  = blockIdx.x * 8 + (threadIdx.x >> 5);
    int lane = threadIdx.x & 31;
    const float* xr = x + (size_t)row * DIN;
    float acc = 0.f;
    #pragma unroll
    for (int d = lane; d < DIN; d += 32) acc += xr[d] * g_wvs[d];
    #pragma unroll
    for (int s = 16; s; s >>= 1) acc += __shfl_xor_sync(0xffffffffu, acc, s);
    if (lane == 0) g_s[row] = acc + g_bvs;
}

// ======================= QK projection: mma.sync bf16 =======================
// C[128 rows, 128 feats] = x[128,512] . W[128,512]^T, two smem K-halves of 256.
#define QK_SMEM (1024 + 65536 + 65536)

__global__ __launch_bounds__(256, 1) void qk_mma(const float* __restrict__ x,
        const float* __restrict__ Wq, const float* __restrict__ bq,
        const float* __restrict__ Wk, const float* __restrict__ bk) {
    extern __shared__ char dsm[];
    uint32_t base0 = s2u(dsm);
    uint32_t A0 = (base0 + 1023u) & ~1023u;
    char* P = dsm + (A0 - base0);

    const int t = threadIdx.x, w = t >> 5, lane = t & 31;
    const int row0 = blockIdx.x * 128;
    int yc = blockIdx.y;
    const float* W; const float* bias; __nv_bfloat16* outp;
    if (yc < 2) { W = Wq; bias = bq; outp = g_qb; }
    else        { W = Wk; bias = bk; outp = g_kb; yc -= 2; }
    const int col0 = yc * 128;

    const uint32_t SA = A0;
    const uint32_t SB = A0 + 65536;
    char* pA = P;
    char* pB = P + 65536;

    const int w16 = w * 16;
    float acc[16][4];
    #pragma unroll
    for (int j = 0; j < 16; j++) { acc[j][0]=0.f; acc[j][1]=0.f; acc[j][2]=0.f; acc[j][3]=0.f; }

    // ldmatrix addresses (per lane, fixed row component)
    const uint32_t arow = (uint32_t)(w16 + ((lane >> 3) & 1) * 8 + (lane & 7));
    const uint32_t ac   = (uint32_t)((lane >> 4) & 1);
    const uint32_t brlo = (uint32_t)(((lane >> 4) & 1) * 8 + (lane & 7));
    const uint32_t bc   = (uint32_t)((lane >> 3) & 1);

    for (int h = 0; h < 2; h++) {
        // fill A (x) and B (W) bf16 swizzled tiles for this K-half
        #pragma unroll
        for (int it = 0; it < 16; it++) {
            int idx = t + it * 256;
            int r = idx >> 5, c = idx & 31;
            const float* ps = x + (size_t)(row0 + r) * DIN + h * 256 + c * 8;
            float4 f0 = *(const float4*)ps;
            float4 f1 = *(const float4*)(ps + 4);
            __nv_bfloat162 h0 = __floats2bfloat162_rn(f0.x, f0.y);
            __nv_bfloat162 h1 = __floats2bfloat162_rn(f0.z, f0.w);
            __nv_bfloat162 h2 = __floats2bfloat162_rn(f1.x, f1.y);
            __nv_bfloat162 h3 = __floats2bfloat162_rn(f1.z, f1.w);
            uint4 u;
            u.x = *(uint32_t*)&h0; u.y = *(uint32_t*)&h1;
            u.z = *(uint32_t*)&h2; u.w = *(uint32_t*)&h3;
            *(uint4*)(pA + sw(r, c)) = u;

            const float* pw = W + (size_t)(col0 + r) * DIN + h * 256 + c * 8;
            f0 = *(const float4*)pw;
            f1 = *(const float4*)(pw + 4);
            h0 = __floats2bfloat162_rn(f0.x, f0.y);
            h1 = __floats2bfloat162_rn(f0.z, f0.w);
            h2 = __floats2bfloat162_rn(f1.x, f1.y);
            h3 = __floats2bfloat162_rn(f1.z, f1.w);
            u.x = *(uint32_t*)&h0; u.y = *(uint32_t*)&h1;
            u.z = *(uint32_t*)&h2; u.w = *(uint32_t*)&h3;
            *(uint4*)(pB + sw(r, c)) = u;
        }
        __syncthreads();

        #pragma unroll
        for (int ks = 0; ks < 16; ks++) {
            uint32_t a0, a1, a2, a3;
            LDSM4(a0, a1, a2, a3, SA + sw(arow, (uint32_t)(ks * 2) + ac));
            #pragma unroll
            for (int nb = 0; nb < 8; nb++) {
                uint32_t b0, b1, b2, b3;
                LDSM4(b0, b1, b2, b3, SB + sw((uint32_t)(nb * 16) + brlo, (uint32_t)(ks * 2) + bc));
                mma16816(acc[nb * 2],     a0, a1, a2, a3, b0, b1);
                mma16816(acc[nb * 2 + 1], a0, a1, a2, a3, b2, b3);
            }
        }
        __syncthreads();
    }

    // epilogue: bias add, bf16 store
    const int r0 = row0 + w16 + (lane >> 2);
    #pragma unroll
    for (int j = 0; j < 16; j++) {
        int col = col0 + j * 8 + (lane & 3) * 2;
        float b0 = __ldg(bias + col), b1 = __ldg(bias + col + 1);
        __nv_bfloat162 lo = __floats2bfloat162_rn(acc[j][0] + b0, acc[j][1] + b1);
        __nv_bfloat162 hi = __floats2bfloat162_rn(acc[j][2] + b0, acc[j][3] + b1);
        *(uint32_t*)(outp + (size_t)r0 * DOUT + col)       = *(uint32_t*)&lo;
        *(uint32_t*)(outp + (size_t)(r0 + 8) * DOUT + col) = *(uint32_t*)&hi;
    }
}

// ======================= fused attention: mma.sync scores + fast-exp epilogue =======================
// smem (from 1024-aligned base):
//   Q 64KB | K0 64KB | K1 64KB | kvall[2048] float2 16KB | g3 rep 2560B
#define AT_Q   0
#define AT_K0  65536
#define AT_K1  131072
#define AT_KV  196608
#define AT_G3  212992
#define ATTN_SMEM (215552 + 1024)

__global__ __launch_bounds__(256, 1) void attn_mma(const long long* __restrict__ pr,
                                                   const float* __restrict__ bs_p,
                                                   float* __restrict__ out) {
    extern __shared__ char dsm[];
    uint32_t base0 = s2u(dsm);
    uint32_t A0 = (base0 + 1023u) & ~1023u;
    char* P = dsm + (A0 - base0);

    const int t = threadIdx.x, w = t >> 5, lane = t & 31;
    const int b = blockIdx.y, n0 = blockIdx.x * 128;

    const uint32_t SQ = A0 + AT_Q;
    const uint32_t SK[2] = { A0 + AT_K0, A0 + AT_K1 };
    float2* kvall = (float2*)(P + AT_KV);   // (s, rank-bits) for all 2048 keys
    float*  g3    = (float*)(P + AT_G3);    // gate LUT replicated 32x

    // initial async loads: Q tile + K tile 0
    const __nv_bfloat16* qsrc = g_qb + ((size_t)b * NN + n0) * DOUT;
    const __nv_bfloat16* ksrc = g_kb + (size_t)b * NN * DOUT;
    #pragma unroll
    for (int it = 0; it < 16; it++) {
        int idx = t + it * 256;
        int r = idx >> 5, c = idx & 31;
        CP16(SQ + sw(r, c), qsrc + (size_t)r * DOUT + c * 8);
        CP16(SK[0] + sw(r, c), ksrc + (size_t)r * DOUT + c * 8);
    }
    CP_COMMIT();

    // kvall + gate LUT (regular loads, overlapped with cp.async)
    #pragma unroll
    for (int it = 0; it < 8; it++) {
        int idx = t + it * 256;
        kvall[idx] = make_float2(g_s[(size_t)b * NN + idx],
                                 __int_as_float((int)pr[(size_t)b * NN + idx]));
    }
    for (int i = t; i < NBUCK * 32; i += 256) g3[i] = g_gate3[i >> 5];

    const int w16 = w * 16;
    const int rn0 = (int)pr[(size_t)b * NN + n0 + w16 + (lane >> 2)];
    const int rn1 = (int)pr[(size_t)b * NN + n0 + w16 + (lane >> 2) + 8];

    // ldmatrix lane-address components
    const uint32_t arow = (uint32_t)(w16 + ((lane >> 3) & 1) * 8 + (lane & 7));
    const uint32_t ac   = (uint32_t)((lane >> 4) & 1);
    const uint32_t brlo = (uint32_t)(((lane >> 4) & 1) * 8 + (lane & 7));
    const uint32_t bc   = (uint32_t)((lane >> 3) & 1);

    float l0 = 0.f, a0s = 0.f, l1 = 0.f, a1s = 0.f;

    CP_WAIT0();
    __syncthreads();

    for (int tile = 0; tile < 16; tile++) {
        const int buf = tile & 1;
        // prefetch next K tile into the other buffer (overlapped with mma+epilogue)
        if (tile + 1 < 16) {
            const __nv_bfloat16* kn = ksrc + (size_t)(tile + 1) * 128 * DOUT;
            #pragma unroll
            for (int it = 0; it < 16; it++) {
                int idx = t + it * 256;
                int r = idx >> 5, c = idx & 31;
                CP16(SK[1 - buf] + sw(r, c), kn + (size_t)r * DOUT + c * 8);
            }
            CP_COMMIT();
        }

        // ---- scores mma: acc[j] covers cols j*8..j*8+7 of this 128-col tile ----
        float acc[16][4];
        #pragma unroll
        for (int j = 0; j < 16; j++) { acc[j][0]=0.f; acc[j][1]=0.f; acc[j][2]=0.f; acc[j][3]=0.f; }

        const uint32_t SKb = SK[buf];
        #pragma unroll
        for (int ks = 0; ks < 16; ks++) {
            uint32_t a0, a1, a2, a3;
            LDSM4(a0, a1, a2, a3, SQ + sw(arow, (uint32_t)(ks * 2) + ac));
            #pragma unroll
            for (int nb = 0; nb < 8; nb++) {
                uint32_t b0, b1, b2, b3;
                LDSM4(b0, b1, b2, b3, SKb + sw((uint32_t)(nb * 16) + brlo, (uint32_t)(ks * 2) + bc));
                mma16816(acc[nb * 2],     a0, a1, a2, a3, b0, b1);
                mma16816(acc[nb * 2 + 1], a0, a1, a2, a3, b2, b3);
            }
        }

        // ---- epilogue: gate + exp + accumulate (no-max softmax, bounded logits) ----
        const float2* kva = kvall + tile * 128;
        #pragma unroll
        for (int j = 0; j < 16; j++) {
            int col = j * 8 + (lane & 3) * 2;
            float2 kv0 = kva[col];
            float2 kv1 = kva[col + 1];
            int rm0 = __float_as_int(kv0.y);
            int rm1 = __float_as_int(kv1.y);
            int d00 = rn0 - rm0; d00 = d00 < 0 ? -d00 : d00;
            int d01 = rn0 - rm1; d01 = d01 < 0 ? -d01 : d01;
            int d10 = rn1 - rm0; d10 = d10 < 0 ? -d10 : d10;
            int d11 = rn1 - rm1; d11 = d11 < 0 ? -d11 : d11;
            unsigned k00 = (unsigned)d00 / 5u; if (k00 > NBUCK-1) k00 = NBUCK-1;
            unsigned k01 = (unsigned)d01 / 5u; if (k01 > NBUCK-1) k01 = NBUCK-1;
            unsigned k10 = (unsigned)d10 / 5u; if (k10 > NBUCK-1) k10 = NBUCK-1;
            unsigned k11 = (unsigned)d11 / 5u; if (k11 > NBUCK-1) k11 = NBUCK-1;
            float e;
            e = exp2_fast(acc[j][0] * g3[k00 * 32 + lane]); l0 += e; a0s = fmaf(e, kv0.x, a0s);
            e = exp2_fast(acc[j][1] * g3[k01 * 32 + lane]); l0 += e; a0s = fmaf(e, kv1.x, a0s);
            e = exp2_fast(acc[j][2] * g3[k10 * 32 + lane]); l1 += e; a1s = fmaf(e, kv0.x, a1s);
            e = exp2_fast(acc[j][3] * g3[k11 * 32 + lane]); l1 += e; a1s = fmaf(e, kv1.x, a1s);
        }

        CP_WAIT0();
        __syncthreads();
    }

    // reduce over the 4 lanes sharing each row, then head
    #pragma unroll
    for (int s = 1; s <= 2; s <<= 1) {
        l0  += __shfl_xor_sync(0xffffffffu, l0,  s);
        a0s += __shfl_xor_sync(0xffffffffu, a0s, s);
        l1  += __shfl_xor_sync(0xffffffffu, l1,  s);
        a1s += __shfl_xor_sync(0xffffffffu, a1s, s);
    }
    if ((lane & 3) == 0) {
        float bsv = bs_p[0];
        int r = n0 + w16 + (lane >> 2);
        float z0 = a0s / l0 + bsv;
        float z1 = a1s / l1 + bsv;
        out[(size_t)b * NN + r]     = 1.f / (1.f + expf(-z0));
        out[(size_t)b * NN + r + 8] = 1.f / (1.f + expf(-z1));
    }
}

// ======================= launcher =======================
extern "C" void kernel_launch(void* const* d_in, const int* in_sizes, int n_in,
                              void* d_out, int out_size) {
    const float*     x    = (const float*)d_in[0];
    const long long* pr   = (const long long*)d_in[1];
    const float*     Wq   = (const float*)d_in[2];
    const float*     bq   = (const float*)d_in[3];
    const float*     Wk   = (const float*)d_in[4];
    const float*     bk   = (const float*)d_in[5];
    const float*     Wv   = (const float*)d_in[6];
    const float*     bv   = (const float*)d_in[7];
    const float*     Ws   = (const float*)d_in[8];
    const float*     bs   = (const float*)d_in[9];
    const float*     remb = (const float*)d_in[10];
    const float*     rw   = (const float*)d_in[11];
    float* out = (float*)d_out;

    prep_kernel<<<1, 512>>>(Wv, bv, Ws, remb, rw);
    s_kernel<<<ROWS/8, 256>>>(x);

    cudaFuncSetAttribute(qk_mma, cudaFuncAttributeMaxDynamicSharedMemorySize, QK_SMEM);
    dim3 g1(ROWS/128, 4);
    qk_mma<<<g1, 256, QK_SMEM>>>(x, Wq, bq, Wk, bk);

    cudaFuncSetAttribute(attn_mma, cudaFuncAttributeMaxDynamicSharedMemorySize, ATTN_SMEM);
    dim3 g2(NN/128, BB);
    attn_mma<<<g2, 256, ATTN_SMEM>>>(pr, bs, out);
}